// round 1
// baseline (speedup 1.0000x reference)
#include <cuda_runtime.h>
#include <math.h>

#define D_MODEL 2048
#define NH      16
#define NKV     4
#define HD      128
#define KV_DIM  512            // NKV * HD
#define QKVW    3072           // D_MODEL + 2*KV_DIM
#define NB      4
#define SEQ     2048
#define TOKENS  (NB * SEQ)     // 8192

// Scratch (allowed: __device__ globals, no runtime allocation)
__device__ float g_qkv [(size_t)TOKENS * QKVW];    // 96 MB
__device__ float g_attn[(size_t)TOKENS * D_MODEL]; // 64 MB

// ---------------------------------------------------------------------------
// SGEMM: C[M,N] = A[M,K] @ B[K,N] + bias[N]; 128x128 tile, 8x8/thread, BK=8
// ---------------------------------------------------------------------------
__global__ __launch_bounds__(256) void sgemm_bias(
    const float* __restrict__ A, const float* __restrict__ B,
    const float* __restrict__ bias, float* __restrict__ C,
    int M, int N, int K)
{
    __shared__ float As[8][128];
    __shared__ float Bs[8][128];

    const int m0 = blockIdx.y * 128;
    const int n0 = blockIdx.x * 128;
    const int tid = threadIdx.x;
    const int ty = tid >> 4;        // 0..15
    const int tx = tid & 15;        // 0..15

    const int arow = tid >> 1;          // 0..127
    const int acol = (tid & 1) * 4;     // 0 or 4
    const int brow = tid >> 5;          // 0..7
    const int bcol = (tid & 31) * 4;    // 0..124

    const float* Aptr = A + (size_t)(m0 + arow) * K + acol;
    const float* Bptr = B + (size_t)brow * N + n0 + bcol;

    float acc[8][8];
    #pragma unroll
    for (int i = 0; i < 8; i++)
        #pragma unroll
        for (int j = 0; j < 8; j++) acc[i][j] = 0.f;

    for (int k0 = 0; k0 < K; k0 += 8) {
        float4 av = *(const float4*)(Aptr + k0);
        float4 bv = *(const float4*)(Bptr + (size_t)k0 * N);
        As[acol + 0][arow] = av.x;
        As[acol + 1][arow] = av.y;
        As[acol + 2][arow] = av.z;
        As[acol + 3][arow] = av.w;
        *(float4*)&Bs[brow][bcol] = bv;
        __syncthreads();

        #pragma unroll
        for (int kk = 0; kk < 8; kk++) {
            float ra[8], rb[8];
            #pragma unroll
            for (int i = 0; i < 8; i++) ra[i] = As[kk][ty * 8 + i];
            #pragma unroll
            for (int j = 0; j < 8; j++) rb[j] = Bs[kk][tx * 8 + j];
            #pragma unroll
            for (int i = 0; i < 8; i++)
                #pragma unroll
                for (int j = 0; j < 8; j++)
                    acc[i][j] = fmaf(ra[i], rb[j], acc[i][j]);
        }
        __syncthreads();
    }

    #pragma unroll
    for (int i = 0; i < 8; i++) {
        const int row = m0 + ty * 8 + i;
        #pragma unroll
        for (int j = 0; j < 8; j += 4) {
            const int col = n0 + tx * 8 + j;
            float4 o;
            o.x = acc[i][j + 0] + bias[col + 0];
            o.y = acc[i][j + 1] + bias[col + 1];
            o.z = acc[i][j + 2] + bias[col + 2];
            o.w = acc[i][j + 3] + bias[col + 3];
            *(float4*)&C[(size_t)row * N + col] = o;
        }
    }
}

// ---------------------------------------------------------------------------
// RMSNorm q and k heads in place. One warp per (token, slot); slots 0..15 = q
// heads, 16..19 = k heads.
// ---------------------------------------------------------------------------
__global__ __launch_bounds__(256) void rmsnorm_qk(
    float* __restrict__ qkv,
    const float* __restrict__ q_scale,
    const float* __restrict__ k_scale)
{
    const int gw   = (blockIdx.x * blockDim.x + threadIdx.x) >> 5;
    const int lane = threadIdx.x & 31;
    const int token = gw / 20;
    const int slot  = gw % 20;
    if (token >= TOKENS) return;

    int col;
    const float* sc;
    if (slot < 16) { col = slot * HD;                      sc = q_scale; }
    else           { col = D_MODEL + (slot - 16) * HD;     sc = k_scale; }

    float* p = qkv + (size_t)token * QKVW + col + lane * 4;
    float4 v = *(float4*)p;
    float ss = v.x * v.x + v.y * v.y + v.z * v.z + v.w * v.w;
    #pragma unroll
    for (int o = 16; o; o >>= 1) ss += __shfl_xor_sync(0xffffffffu, ss, o);
    const float r = rsqrtf(ss * (1.0f / HD) + 1e-6f);
    const float4 s4 = *(const float4*)(sc + lane * 4);
    v.x *= r * s4.x; v.y *= r * s4.y; v.z *= r * s4.z; v.w *= r * s4.w;
    *(float4*)p = v;
}

// ---------------------------------------------------------------------------
// Causal flash attention, fp32. Block = 256 threads, Bq = Bk = 64, hd = 128.
// Q,K stored d-major in smem (K stride 65 for bank spread), V row-major,
// S tile stride 65. GQA: head h uses kv head h/4.
// ---------------------------------------------------------------------------
#define BQ 64
#define BK 64
#define KT_S 65   // Kt row stride
#define SS_S 65   // S tile row stride

__global__ __launch_bounds__(256) void flash_attn(
    const float* __restrict__ qkv, float* __restrict__ out)
{
    extern __shared__ float sm[];
    float* Qt = sm;                    // [128][64]   d-major
    float* Kt = Qt + 128 * 64;         // [128][65]   d-major, padded
    float* Vs = Kt + 128 * KT_S;       // [64][128]   row-major
    float* Ss = Vs + 64 * 128;         // [64][65]

    const int qb = blockIdx.x;
    const int h  = blockIdx.y;
    const int n  = blockIdx.z;
    const int kvh = h >> 2;
    const int q0 = qb * BQ;
    const int tid = threadIdx.x;

    const float* base = qkv + (size_t)n * SEQ * QKVW;
    const int qcol = h * HD;
    const int kcol = D_MODEL + kvh * HD;
    const int vcol = D_MODEL + KV_DIM + kvh * HD;

    // Load Q tile transposed: Qt[d][r]
    for (int i = tid * 4; i < BQ * HD; i += 1024) {
        const int r = i >> 7, c = i & 127;
        const float4 q4 = *(const float4*)&base[(size_t)(q0 + r) * QKVW + qcol + c];
        Qt[(c + 0) * 64 + r] = q4.x;
        Qt[(c + 1) * 64 + r] = q4.y;
        Qt[(c + 2) * 64 + r] = q4.z;
        Qt[(c + 3) * 64 + r] = q4.w;
    }

    // S-compute mapping: 4x4 register tile per thread
    const int si0 = ((tid >> 4) & 15) << 2;   // 0..60
    const int sj0 = (tid & 15) << 2;          // 0..60
    // O / softmax mapping: row + interleaved column groups
    const int orow = tid >> 2;                // 0..63
    const int ocg  = tid & 3;                 // 0..3

    float m = -1e30f, lsum = 0.f;
    float acc[32];
    #pragma unroll
    for (int i = 0; i < 32; i++) acc[i] = 0.f;

    const float scale = 0.08838834764831843f; // 1/sqrt(128)

    for (int k0 = 0; k0 <= q0; k0 += BK) {
        __syncthreads();
        // Load K (transposed, padded) and V (row-major)
        for (int i = tid * 4; i < BK * HD; i += 1024) {
            const int r = i >> 7, c = i & 127;
            const size_t rowoff = (size_t)(k0 + r) * QKVW;
            const float4 k4 = *(const float4*)&base[rowoff + kcol + c];
            const float4 v4 = *(const float4*)&base[rowoff + vcol + c];
            Kt[(c + 0) * KT_S + r] = k4.x;
            Kt[(c + 1) * KT_S + r] = k4.y;
            Kt[(c + 2) * KT_S + r] = k4.z;
            Kt[(c + 3) * KT_S + r] = k4.w;
            *(float4*)&Vs[r * 128 + c] = v4;
        }
        __syncthreads();

        // S = Q @ K^T (4x4 per thread)
        float s[4][4];
        #pragma unroll
        for (int a = 0; a < 4; a++)
            #pragma unroll
            for (int b = 0; b < 4; b++) s[a][b] = 0.f;

        #pragma unroll 2
        for (int d = 0; d < HD; d++) {
            const float4 qv = *(const float4*)&Qt[d * 64 + si0];
            const float kv0 = Kt[d * KT_S + sj0 + 0];
            const float kv1 = Kt[d * KT_S + sj0 + 1];
            const float kv2 = Kt[d * KT_S + sj0 + 2];
            const float kv3 = Kt[d * KT_S + sj0 + 3];
            s[0][0] = fmaf(qv.x, kv0, s[0][0]); s[0][1] = fmaf(qv.x, kv1, s[0][1]);
            s[0][2] = fmaf(qv.x, kv2, s[0][2]); s[0][3] = fmaf(qv.x, kv3, s[0][3]);
            s[1][0] = fmaf(qv.y, kv0, s[1][0]); s[1][1] = fmaf(qv.y, kv1, s[1][1]);
            s[1][2] = fmaf(qv.y, kv2, s[1][2]); s[1][3] = fmaf(qv.y, kv3, s[1][3]);
            s[2][0] = fmaf(qv.z, kv0, s[2][0]); s[2][1] = fmaf(qv.z, kv1, s[2][1]);
            s[2][2] = fmaf(qv.z, kv2, s[2][2]); s[2][3] = fmaf(qv.z, kv3, s[2][3]);
            s[3][0] = fmaf(qv.w, kv0, s[3][0]); s[3][1] = fmaf(qv.w, kv1, s[3][1]);
            s[3][2] = fmaf(qv.w, kv2, s[3][2]); s[3][3] = fmaf(qv.w, kv3, s[3][3]);
        }

        // Scale + causal mask -> Ss
        #pragma unroll
        for (int a = 0; a < 4; a++)
            #pragma unroll
            for (int b = 0; b < 4; b++) {
                float v = s[a][b] * scale;
                if (k0 + sj0 + b > q0 + si0 + a) v = -1e30f;
                Ss[(si0 + a) * SS_S + sj0 + b] = v;
            }
        __syncthreads();

        // Online softmax for row `orow`, quarter `ocg`
        const int cbase = ocg * 16;
        float pm = -1e30f;
        #pragma unroll
        for (int j = 0; j < 16; j++) pm = fmaxf(pm, Ss[orow * SS_S + cbase + j]);
        pm = fmaxf(pm, __shfl_xor_sync(0xffffffffu, pm, 1));
        pm = fmaxf(pm, __shfl_xor_sync(0xffffffffu, pm, 2));
        const float mnew = fmaxf(m, pm);
        const float corr = __expf(m - mnew);
        float ps = 0.f;
        #pragma unroll
        for (int j = 0; j < 16; j++) {
            const float p = __expf(Ss[orow * SS_S + cbase + j] - mnew);
            Ss[orow * SS_S + cbase + j] = p;
            ps += p;
        }
        ps += __shfl_xor_sync(0xffffffffu, ps, 1);
        ps += __shfl_xor_sync(0xffffffffu, ps, 2);
        lsum = lsum * corr + ps;
        m = mnew;
        #pragma unroll
        for (int c = 0; c < 32; c++) acc[c] *= corr;
        __syncthreads();

        // O += P @ V ; thread owns cols {16k + 4*ocg + cc}
        #pragma unroll 2
        for (int j = 0; j < BK; j++) {
            const float p = Ss[orow * SS_S + j];
            const float* vr = &Vs[j * 128 + ocg * 4];
            #pragma unroll
            for (int k = 0; k < 8; k++) {
                const float4 v4 = *(const float4*)&vr[k * 16];
                acc[k * 4 + 0] = fmaf(p, v4.x, acc[k * 4 + 0]);
                acc[k * 4 + 1] = fmaf(p, v4.y, acc[k * 4 + 1]);
                acc[k * 4 + 2] = fmaf(p, v4.z, acc[k * 4 + 2]);
                acc[k * 4 + 3] = fmaf(p, v4.w, acc[k * 4 + 3]);
            }
        }
    }

    // Epilogue: normalize and write [N, L, H*hd]
    const float inv = 1.0f / lsum;
    float* op = out + ((size_t)(n * SEQ + q0 + orow)) * D_MODEL + h * HD + ocg * 4;
    #pragma unroll
    for (int k = 0; k < 8; k++) {
        float4 o;
        o.x = acc[k * 4 + 0] * inv;
        o.y = acc[k * 4 + 1] * inv;
        o.z = acc[k * 4 + 2] * inv;
        o.w = acc[k * 4 + 3] * inv;
        *(float4*)&op[k * 16] = o;
    }
}

// ---------------------------------------------------------------------------
extern "C" void kernel_launch(void* const* d_in, const int* in_sizes, int n_in,
                              void* d_out, int out_size)
{
    const float* x       = (const float*)d_in[0];
    const float* Wqkv    = (const float*)d_in[1];
    const float* bqkv    = (const float*)d_in[2];
    const float* q_scale = (const float*)d_in[3];
    const float* k_scale = (const float*)d_in[4];
    const float* Wout    = (const float*)d_in[5];
    const float* bout    = (const float*)d_in[6];
    float* out = (float*)d_out;

    float *qkv, *attn;
    cudaGetSymbolAddress((void**)&qkv,  g_qkv);
    cudaGetSymbolAddress((void**)&attn, g_attn);

    // 1) QKV projection: [8192,2048] @ [2048,3072] + bqkv
    sgemm_bias<<<dim3(QKVW / 128, TOKENS / 128), 256>>>(
        x, Wqkv, bqkv, qkv, TOKENS, QKVW, D_MODEL);

    // 2) RMSNorm q/k heads in place
    rmsnorm_qk<<<(TOKENS * 20) / 8, 256>>>(qkv, q_scale, k_scale);

    // 3) Causal flash attention -> attn [8192, 2048]
    const int attn_smem = (128 * 64 + 128 * KT_S + 64 * 128 + 64 * SS_S) * (int)sizeof(float);
    cudaFuncSetAttribute(flash_attn, cudaFuncAttributeMaxDynamicSharedMemorySize, attn_smem);
    flash_attn<<<dim3(SEQ / BQ, NH, NB), 256, attn_smem>>>(qkv, attn);

    // 4) Output projection: [8192,2048] @ [2048,2048] + bout
    sgemm_bias<<<dim3(D_MODEL / 128, TOKENS / 128), 256>>>(
        attn, Wout, bout, out, TOKENS, D_MODEL, D_MODEL);
}

// round 3
// speedup vs baseline: 1.5780x; 1.5780x over previous
#include <cuda_runtime.h>
#include <math.h>
#include <stdint.h>

#define D_MODEL 2048
#define NH      16
#define NKV     4
#define HD      128
#define KV_DIM  512
#define QKVW    3072
#define NB      4
#define SEQ     2048
#define TOKENS  (NB * SEQ)
#define KDIM    2048

// Scratch (device globals — no runtime allocation)
__device__ float g_qkv  [(size_t)TOKENS * QKVW];
__device__ float g_attn [(size_t)TOKENS * D_MODEL];
__device__ float g_xc   [(size_t)TOKENS * D_MODEL];
__device__ float g_wqkvT[(size_t)QKVW   * D_MODEL];
__device__ float g_woutT[(size_t)D_MODEL* D_MODEL];

// ---------------------------------------------------------------------------
// Helpers (base-target PTX only: mma.sync / ldmatrix / cp.async / cvt.tf32)
// ---------------------------------------------------------------------------
__device__ __forceinline__ uint32_t smem_u32(const void* p) {
    uint32_t r;
    asm("{ .reg .u64 t; cvta.to.shared.u64 t, %1; cvt.u32.u64 %0, t; }" : "=r"(r) : "l"(p));
    return r;
}
__device__ __forceinline__ void cp16(uint32_t d, const void* s) {
    asm volatile("cp.async.cg.shared.global [%0], [%1], 16;" :: "r"(d), "l"(s));
}
__device__ __forceinline__ void cp_commit() {
    asm volatile("cp.async.commit_group;" ::: "memory");
}
template<int N> __device__ __forceinline__ void cp_wait() {
    asm volatile("cp.async.wait_group %0;" :: "n"(N) : "memory");
}
__device__ __forceinline__ void ldm_x4(uint32_t* r, uint32_t addr) {
    asm volatile("ldmatrix.sync.aligned.m8n8.x4.shared.b16 {%0,%1,%2,%3}, [%4];"
        : "=r"(r[0]), "=r"(r[1]), "=r"(r[2]), "=r"(r[3]) : "r"(addr));
}
__device__ __forceinline__ void mma_tf32(float* c, const uint32_t* a, const uint32_t* b) {
    asm volatile(
        "mma.sync.aligned.m16n8k8.row.col.f32.tf32.tf32.f32 "
        "{%0,%1,%2,%3}, {%4,%5,%6,%7}, {%8,%9}, {%0,%1,%2,%3};"
        : "+f"(c[0]), "+f"(c[1]), "+f"(c[2]), "+f"(c[3])
        : "r"(a[0]), "r"(a[1]), "r"(a[2]), "r"(a[3]), "r"(b[0]), "r"(b[1]));
}
__device__ __forceinline__ float to_tf32(float v) {
    uint32_t u;
    asm("cvt.rna.tf32.f32 %0, %1;" : "=r"(u) : "f"(v));
    return __uint_as_float(u);
}

// ---------------------------------------------------------------------------
// TF32 tensor-core GEMM: C[M,N] = A[M,K] @ Bt[N,K]^T + bias
// CTA 128x128, BK=32, 3-stage cp.async, 8 warps x (64x32), m16n8k8 mma.
// A, Bt pre-rounded to tf32. LDA=36 floats (144B rows, 16B aligned, no-conflict).
// ---------------------------------------------------------------------------
#define BKG  32
#define GSTG 3
#define LDA  36
#define STAGE_F (128 * LDA)

__global__ __launch_bounds__(256) void gemm_mma(
    const float* __restrict__ A, const float* __restrict__ Bt,
    const float* __restrict__ bias, float* __restrict__ C,
    int N, int K)
{
    extern __shared__ __align__(16) float sh[];
    float* As = sh;                       // [GSTG][128*LDA]
    float* Bs = sh + GSTG * STAGE_F;

    const int tid  = threadIdx.x;
    const int wid  = tid >> 5, lane = tid & 31;
    const int wm   = wid >> 2, wn = wid & 3;       // warp grid 2 x 4
    const int gid  = lane >> 2, tig = lane & 3;
    const int m0   = blockIdx.y * 128, n0 = blockIdx.x * 128;
    const int NC   = K / BKG;

    const uint32_t sA = smem_u32(As);
    const uint32_t sB = smem_u32(Bs);

    // ldmatrix lane->address offsets
    const int a_row = (lane & 7) + ((lane >> 3) & 1) * 8;   // row within 16-row tile
    const int a_col = (lane >> 4) * 4;                      // 0 or 4
    const int b_row = (lane & 7) + ((lane >> 4) & 1) * 8;   // row within 16-n block
    const int b_col = ((lane >> 3) & 1) * 4;                // 0 or 4

    // global load mapping: 4 x 16B for A + 4 x 16B for B per stage
    const int g_row  = (tid >> 1);              // used via blk decomposition below

    float acc[4][4][4];
    #pragma unroll
    for (int i = 0; i < 4; i++)
        #pragma unroll
        for (int j = 0; j < 4; j++)
            #pragma unroll
            for (int t = 0; t < 4; t++) acc[i][j][t] = 0.f;
    (void)g_row;

    auto issue = [&](int c) {
        const int s = c % GSTG;
        const float* Ag = A  + (size_t)m0 * K + c * BKG;
        const float* Bg = Bt + (size_t)n0 * K + c * BKG;
        const uint32_t Ad = sA + s * STAGE_F * 4;
        const uint32_t Bd = sB + s * STAGE_F * 4;
        #pragma unroll
        for (int it = 0; it < 4; it++) {
            const int blk = tid + it * 256;        // 0..1023
            const int row = blk >> 3, quad = blk & 7;
            cp16(Ad + (row * LDA + quad * 4) * 4, Ag + (size_t)row * K + quad * 4);
            cp16(Bd + (row * LDA + quad * 4) * 4, Bg + (size_t)row * K + quad * 4);
        }
        cp_commit();
    };

    // prologue: GSTG-1 chunks in flight
    issue(0);
    issue(1);

    for (int c = 0; c < NC; c++) {
        if (c + 1 == NC) cp_wait<0>(); else cp_wait<GSTG - 2>();
        __syncthreads();

        const int s = c % GSTG;
        const uint32_t Abase = sA + (s * STAGE_F + (wm * 64 + a_row) * LDA + a_col) * 4;
        const uint32_t Bbase = sB + (s * STAGE_F + (wn * 32 + b_row) * LDA + b_col) * 4;

        #pragma unroll
        for (int k8 = 0; k8 < 4; k8++) {
            uint32_t a[4][4], b[2][4];
            #pragma unroll
            for (int i = 0; i < 4; i++)
                ldm_x4(a[i], Abase + (i * 16 * LDA + k8 * 8) * 4);
            #pragma unroll
            for (int j2 = 0; j2 < 2; j2++)
                ldm_x4(b[j2], Bbase + (j2 * 16 * LDA + k8 * 8) * 4);
            #pragma unroll
            for (int i = 0; i < 4; i++) {
                #pragma unroll
                for (int j = 0; j < 4; j++)
                    mma_tf32(acc[i][j], a[i], &b[j >> 1][(j & 1) * 2]);
            }
        }
        __syncthreads();
        if (c + GSTG - 1 < NC) issue(c + GSTG - 1);
    }

    // epilogue: c-frag rows gid/gid+8, cols tig*2, tig*2+1
    #pragma unroll
    for (int j = 0; j < 4; j++) {
        const int col = n0 + wn * 32 + j * 8 + tig * 2;
        const float2 bz = *(const float2*)&bias[col];
        #pragma unroll
        for (int i = 0; i < 4; i++) {
            const int r0 = m0 + wm * 64 + i * 16 + gid;
            float2 o0, o1;
            o0.x = acc[i][j][0] + bz.x;  o0.y = acc[i][j][1] + bz.y;
            o1.x = acc[i][j][2] + bz.x;  o1.y = acc[i][j][3] + bz.y;
            *(float2*)&C[(size_t)r0 * N + col]       = o0;
            *(float2*)&C[(size_t)(r0 + 8) * N + col] = o1;
        }
    }
}

// ---------------------------------------------------------------------------
// Prep: tf32 rounding + weight transpose (-> K-major Bt)
// ---------------------------------------------------------------------------
__global__ __launch_bounds__(256) void cvt_x_tf32(const float* __restrict__ in,
                                                  float* __restrict__ out, int n4)
{
    int i = blockIdx.x * 256 + threadIdx.x;
    if (i >= n4) return;
    float4 v = ((const float4*)in)[i];
    v.x = to_tf32(v.x); v.y = to_tf32(v.y); v.z = to_tf32(v.z); v.w = to_tf32(v.w);
    ((float4*)out)[i] = v;
}

__global__ __launch_bounds__(256) void transpose_tf32(const float* __restrict__ W,
                                                      float* __restrict__ Wt, int K, int N)
{
    __shared__ float t[32][33];
    const int nb = blockIdx.x * 32, kb = blockIdx.y * 32;
    const int x = threadIdx.x & 31, y4 = (threadIdx.x >> 5) * 4;
    #pragma unroll
    for (int i = 0; i < 4; i++) t[y4 + i][x] = W[(size_t)(kb + y4 + i) * N + nb + x];
    __syncthreads();
    #pragma unroll
    for (int i = 0; i < 4; i++)
        Wt[(size_t)(nb + y4 + i) * K + kb + x] = to_tf32(t[x][y4 + i]);
}

// ---------------------------------------------------------------------------
// RMSNorm q/k heads in place (fp32)
// ---------------------------------------------------------------------------
__global__ __launch_bounds__(256) void rmsnorm_qk(
    float* __restrict__ qkv, const float* __restrict__ q_scale, const float* __restrict__ k_scale)
{
    const int gw   = (blockIdx.x * blockDim.x + threadIdx.x) >> 5;
    const int lane = threadIdx.x & 31;
    const int token = gw / 20;
    const int slot  = gw % 20;
    if (token >= TOKENS) return;

    int col; const float* sc;
    if (slot < 16) { col = slot * HD;                  sc = q_scale; }
    else           { col = D_MODEL + (slot - 16) * HD; sc = k_scale; }

    float* p = qkv + (size_t)token * QKVW + col + lane * 4;
    float4 v = *(float4*)p;
    float ss = v.x * v.x + v.y * v.y + v.z * v.z + v.w * v.w;
    #pragma unroll
    for (int o = 16; o; o >>= 1) ss += __shfl_xor_sync(0xffffffffu, ss, o);
    const float r = rsqrtf(ss * (1.0f / HD) + 1e-6f);
    const float4 s4 = *(const float4*)(sc + lane * 4);
    v.x *= r * s4.x; v.y *= r * s4.y; v.z *= r * s4.z; v.w *= r * s4.w;
    *(float4*)p = v;
}

// ---------------------------------------------------------------------------
// Causal flash attention, fp32 (passing R1 version; epilogue rounds to tf32)
// ---------------------------------------------------------------------------
#define BQ 64
#define BK 64
#define KT_S 65
#define SS_S 65

__global__ __launch_bounds__(256) void flash_attn(
    const float* __restrict__ qkv, float* __restrict__ out)
{
    extern __shared__ float sm[];
    float* Qt = sm;
    float* Kt = Qt + 128 * 64;
    float* Vs = Kt + 128 * KT_S;
    float* Ss = Vs + 64 * 128;

    const int qb = blockIdx.x, h = blockIdx.y, n = blockIdx.z;
    const int kvh = h >> 2;
    const int q0 = qb * BQ;
    const int tid = threadIdx.x;

    const float* base = qkv + (size_t)n * SEQ * QKVW;
    const int qcol = h * HD;
    const int kcol = D_MODEL + kvh * HD;
    const int vcol = D_MODEL + KV_DIM + kvh * HD;

    for (int i = tid * 4; i < BQ * HD; i += 1024) {
        const int r = i >> 7, c = i & 127;
        const float4 q4 = *(const float4*)&base[(size_t)(q0 + r) * QKVW + qcol + c];
        Qt[(c + 0) * 64 + r] = q4.x;
        Qt[(c + 1) * 64 + r] = q4.y;
        Qt[(c + 2) * 64 + r] = q4.z;
        Qt[(c + 3) * 64 + r] = q4.w;
    }

    const int si0 = ((tid >> 4) & 15) << 2;
    const int sj0 = (tid & 15) << 2;
    const int orow = tid >> 2;
    const int ocg  = tid & 3;

    float m = -1e30f, lsum = 0.f;
    float acc[32];
    #pragma unroll
    for (int i = 0; i < 32; i++) acc[i] = 0.f;

    const float scale = 0.08838834764831843f;

    for (int k0 = 0; k0 <= q0; k0 += BK) {
        __syncthreads();
        for (int i = tid * 4; i < BK * HD; i += 1024) {
            const int r = i >> 7, c = i & 127;
            const size_t rowoff = (size_t)(k0 + r) * QKVW;
            const float4 k4 = *(const float4*)&base[rowoff + kcol + c];
            const float4 v4 = *(const float4*)&base[rowoff + vcol + c];
            Kt[(c + 0) * KT_S + r] = k4.x;
            Kt[(c + 1) * KT_S + r] = k4.y;
            Kt[(c + 2) * KT_S + r] = k4.z;
            Kt[(c + 3) * KT_S + r] = k4.w;
            *(float4*)&Vs[r * 128 + c] = v4;
        }
        __syncthreads();

        float s[4][4];
        #pragma unroll
        for (int a = 0; a < 4; a++)
            #pragma unroll
            for (int b = 0; b < 4; b++) s[a][b] = 0.f;

        #pragma unroll 2
        for (int d = 0; d < HD; d++) {
            const float4 qv = *(const float4*)&Qt[d * 64 + si0];
            const float kv0 = Kt[d * KT_S + sj0 + 0];
            const float kv1 = Kt[d * KT_S + sj0 + 1];
            const float kv2 = Kt[d * KT_S + sj0 + 2];
            const float kv3 = Kt[d * KT_S + sj0 + 3];
            s[0][0] = fmaf(qv.x, kv0, s[0][0]); s[0][1] = fmaf(qv.x, kv1, s[0][1]);
            s[0][2] = fmaf(qv.x, kv2, s[0][2]); s[0][3] = fmaf(qv.x, kv3, s[0][3]);
            s[1][0] = fmaf(qv.y, kv0, s[1][0]); s[1][1] = fmaf(qv.y, kv1, s[1][1]);
            s[1][2] = fmaf(qv.y, kv2, s[1][2]); s[1][3] = fmaf(qv.y, kv3, s[1][3]);
            s[2][0] = fmaf(qv.z, kv0, s[2][0]); s[2][1] = fmaf(qv.z, kv1, s[2][1]);
            s[2][2] = fmaf(qv.z, kv2, s[2][2]); s[2][3] = fmaf(qv.z, kv3, s[2][3]);
            s[3][0] = fmaf(qv.w, kv0, s[3][0]); s[3][1] = fmaf(qv.w, kv1, s[3][1]);
            s[3][2] = fmaf(qv.w, kv2, s[3][2]); s[3][3] = fmaf(qv.w, kv3, s[3][3]);
        }

        #pragma unroll
        for (int a = 0; a < 4; a++)
            #pragma unroll
            for (int b = 0; b < 4; b++) {
                float v = s[a][b] * scale;
                if (k0 + sj0 + b > q0 + si0 + a) v = -1e30f;
                Ss[(si0 + a) * SS_S + sj0 + b] = v;
            }
        __syncthreads();

        const int cbase = ocg * 16;
        float pm = -1e30f;
        #pragma unroll
        for (int j = 0; j < 16; j++) pm = fmaxf(pm, Ss[orow * SS_S + cbase + j]);
        pm = fmaxf(pm, __shfl_xor_sync(0xffffffffu, pm, 1));
        pm = fmaxf(pm, __shfl_xor_sync(0xffffffffu, pm, 2));
        const float mnew = fmaxf(m, pm);
        const float corr = __expf(m - mnew);
        float ps = 0.f;
        #pragma unroll
        for (int j = 0; j < 16; j++) {
            const float p = __expf(Ss[orow * SS_S + cbase + j] - mnew);
            Ss[orow * SS_S + cbase + j] = p;
            ps += p;
        }
        ps += __shfl_xor_sync(0xffffffffu, ps, 1);
        ps += __shfl_xor_sync(0xffffffffu, ps, 2);
        lsum = lsum * corr + ps;
        m = mnew;
        #pragma unroll
        for (int c = 0; c < 32; c++) acc[c] *= corr;
        __syncthreads();

        #pragma unroll 2
        for (int j = 0; j < BK; j++) {
            const float p = Ss[orow * SS_S + j];
            const float* vr = &Vs[j * 128 + ocg * 4];
            #pragma unroll
            for (int k = 0; k < 8; k++) {
                const float4 v4 = *(const float4*)&vr[k * 16];
                acc[k * 4 + 0] = fmaf(p, v4.x, acc[k * 4 + 0]);
                acc[k * 4 + 1] = fmaf(p, v4.y, acc[k * 4 + 1]);
                acc[k * 4 + 2] = fmaf(p, v4.z, acc[k * 4 + 2]);
                acc[k * 4 + 3] = fmaf(p, v4.w, acc[k * 4 + 3]);
            }
        }
    }

    const float inv = 1.0f / lsum;
    float* op = out + ((size_t)(n * SEQ + q0 + orow)) * D_MODEL + h * HD + ocg * 4;
    #pragma unroll
    for (int k = 0; k < 8; k++) {
        float4 o;
        o.x = to_tf32(acc[k * 4 + 0] * inv);
        o.y = to_tf32(acc[k * 4 + 1] * inv);
        o.z = to_tf32(acc[k * 4 + 2] * inv);
        o.w = to_tf32(acc[k * 4 + 3] * inv);
        *(float4*)&op[k * 16] = o;
    }
}

// ---------------------------------------------------------------------------
extern "C" void kernel_launch(void* const* d_in, const int* in_sizes, int n_in,
                              void* d_out, int out_size)
{
    const float* x       = (const float*)d_in[0];
    const float* Wqkv    = (const float*)d_in[1];
    const float* bqkv    = (const float*)d_in[2];
    const float* q_scale = (const float*)d_in[3];
    const float* k_scale = (const float*)d_in[4];
    const float* Wout    = (const float*)d_in[5];
    const float* bout    = (const float*)d_in[6];
    float* out = (float*)d_out;

    float *qkv, *attn, *xc, *wqT, *woT;
    cudaGetSymbolAddress((void**)&qkv,  g_qkv);
    cudaGetSymbolAddress((void**)&attn, g_attn);
    cudaGetSymbolAddress((void**)&xc,   g_xc);
    cudaGetSymbolAddress((void**)&wqT,  g_wqkvT);
    cudaGetSymbolAddress((void**)&woT,  g_woutT);

    // Prep: tf32-round x, transpose+round weights
    cvt_x_tf32<<<(TOKENS * D_MODEL / 4 + 255) / 256, 256>>>(x, xc, TOKENS * D_MODEL / 4);
    transpose_tf32<<<dim3(QKVW / 32, KDIM / 32), 256>>>(Wqkv, wqT, KDIM, QKVW);
    transpose_tf32<<<dim3(D_MODEL / 32, KDIM / 32), 256>>>(Wout, woT, KDIM, D_MODEL);

    const int gsmem = GSTG * STAGE_F * 2 * (int)sizeof(float);  // 110,592 B
    cudaFuncSetAttribute(gemm_mma, cudaFuncAttributeMaxDynamicSharedMemorySize, gsmem);

    // 1) QKV projection (tensor-core tf32)
    gemm_mma<<<dim3(QKVW / 128, TOKENS / 128), 256, gsmem>>>(xc, wqT, bqkv, qkv, QKVW, KDIM);

    // 2) RMSNorm q/k heads
    rmsnorm_qk<<<(TOKENS * 20) / 8, 256>>>(qkv, q_scale, k_scale);

    // 3) Causal flash attention (fp32)
    const int attn_smem = (128 * 64 + 128 * KT_S + 64 * 128 + 64 * SS_S) * (int)sizeof(float);
    cudaFuncSetAttribute(flash_attn, cudaFuncAttributeMaxDynamicSharedMemorySize, attn_smem);
    flash_attn<<<dim3(SEQ / BQ, NH, NB), 256, attn_smem>>>(qkv, attn);

    // 4) Output projection (tensor-core tf32)
    gemm_mma<<<dim3(D_MODEL / 128, TOKENS / 128), 256, gsmem>>>(attn, woT, bout, out, D_MODEL, KDIM);
}

// round 4
// speedup vs baseline: 4.3688x; 2.7685x over previous
#include <cuda_runtime.h>
#include <math.h>
#include <stdint.h>

#define D_MODEL 2048
#define NH      16
#define NKV     4
#define HD      128
#define KV_DIM  512
#define QKVW    3072
#define NB      4
#define SEQ     2048
#define TOKENS  (NB * SEQ)
#define KDIM    2048

// Scratch (device globals — no runtime allocation)
__device__ float g_qkv  [(size_t)TOKENS * QKVW];
__device__ float g_attn [(size_t)TOKENS * D_MODEL];
__device__ float g_xc   [(size_t)TOKENS * D_MODEL];
__device__ float g_wqkvT[(size_t)QKVW   * D_MODEL];
__device__ float g_woutT[(size_t)D_MODEL* D_MODEL];

// ---------------------------------------------------------------------------
// Helpers (base-target PTX only: mma.sync / ldmatrix / cp.async / cvt.tf32)
// ---------------------------------------------------------------------------
__device__ __forceinline__ uint32_t smem_u32(const void* p) {
    uint32_t r;
    asm("{ .reg .u64 t; cvta.to.shared.u64 t, %1; cvt.u32.u64 %0, t; }" : "=r"(r) : "l"(p));
    return r;
}
__device__ __forceinline__ void cp16(uint32_t d, const void* s) {
    asm volatile("cp.async.cg.shared.global [%0], [%1], 16;" :: "r"(d), "l"(s));
}
__device__ __forceinline__ void cp_commit() {
    asm volatile("cp.async.commit_group;" ::: "memory");
}
template<int N> __device__ __forceinline__ void cp_wait() {
    asm volatile("cp.async.wait_group %0;" :: "n"(N) : "memory");
}
__device__ __forceinline__ void ldm_x4(uint32_t* r, uint32_t addr) {
    asm volatile("ldmatrix.sync.aligned.m8n8.x4.shared.b16 {%0,%1,%2,%3}, [%4];"
        : "=r"(r[0]), "=r"(r[1]), "=r"(r[2]), "=r"(r[3]) : "r"(addr));
}
__device__ __forceinline__ void mma_tf32(float* c, const uint32_t* a, const uint32_t* b) {
    asm volatile(
        "mma.sync.aligned.m16n8k8.row.col.f32.tf32.tf32.f32 "
        "{%0,%1,%2,%3}, {%4,%5,%6,%7}, {%8,%9}, {%0,%1,%2,%3};"
        : "+f"(c[0]), "+f"(c[1]), "+f"(c[2]), "+f"(c[3])
        : "r"(a[0]), "r"(a[1]), "r"(a[2]), "r"(a[3]), "r"(b[0]), "r"(b[1]));
}
__device__ __forceinline__ float to_tf32(float v) {
    uint32_t u;
    asm("cvt.rna.tf32.f32 %0, %1;" : "=r"(u) : "f"(v));
    return __uint_as_float(u);
}

// ---------------------------------------------------------------------------
// TF32 tensor-core GEMM (unchanged from R3): C = A @ Bt^T + bias
// ---------------------------------------------------------------------------
#define BKG  32
#define GSTG 3
#define LDA  36
#define STAGE_F (128 * LDA)

__global__ __launch_bounds__(256) void gemm_mma(
    const float* __restrict__ A, const float* __restrict__ Bt,
    const float* __restrict__ bias, float* __restrict__ C,
    int N, int K)
{
    extern __shared__ __align__(16) float sh[];
    float* As = sh;
    float* Bs = sh + GSTG * STAGE_F;

    const int tid  = threadIdx.x;
    const int wid  = tid >> 5, lane = tid & 31;
    const int wm   = wid >> 2, wn = wid & 3;
    const int gid  = lane >> 2, tig = lane & 3;
    const int m0   = blockIdx.y * 128, n0 = blockIdx.x * 128;
    const int NC   = K / BKG;

    const uint32_t sA = smem_u32(As);
    const uint32_t sB = smem_u32(Bs);

    const int a_row = (lane & 7) + ((lane >> 3) & 1) * 8;
    const int a_col = (lane >> 4) * 4;
    const int b_row = (lane & 7) + ((lane >> 4) & 1) * 8;
    const int b_col = ((lane >> 3) & 1) * 4;

    float acc[4][4][4];
    #pragma unroll
    for (int i = 0; i < 4; i++)
        #pragma unroll
        for (int j = 0; j < 4; j++)
            #pragma unroll
            for (int t = 0; t < 4; t++) acc[i][j][t] = 0.f;

    auto issue = [&](int c) {
        const int s = c % GSTG;
        const float* Ag = A  + (size_t)m0 * K + c * BKG;
        const float* Bg = Bt + (size_t)n0 * K + c * BKG;
        const uint32_t Ad = sA + s * STAGE_F * 4;
        const uint32_t Bd = sB + s * STAGE_F * 4;
        #pragma unroll
        for (int it = 0; it < 4; it++) {
            const int blk = tid + it * 256;
            const int row = blk >> 3, quad = blk & 7;
            cp16(Ad + (row * LDA + quad * 4) * 4, Ag + (size_t)row * K + quad * 4);
            cp16(Bd + (row * LDA + quad * 4) * 4, Bg + (size_t)row * K + quad * 4);
        }
        cp_commit();
    };

    issue(0);
    issue(1);

    for (int c = 0; c < NC; c++) {
        if (c + 1 == NC) cp_wait<0>(); else cp_wait<GSTG - 2>();
        __syncthreads();

        const int s = c % GSTG;
        const uint32_t Abase = sA + (s * STAGE_F + (wm * 64 + a_row) * LDA + a_col) * 4;
        const uint32_t Bbase = sB + (s * STAGE_F + (wn * 32 + b_row) * LDA + b_col) * 4;

        #pragma unroll
        for (int k8 = 0; k8 < 4; k8++) {
            uint32_t a[4][4], b[2][4];
            #pragma unroll
            for (int i = 0; i < 4; i++)
                ldm_x4(a[i], Abase + (i * 16 * LDA + k8 * 8) * 4);
            #pragma unroll
            for (int j2 = 0; j2 < 2; j2++)
                ldm_x4(b[j2], Bbase + (j2 * 16 * LDA + k8 * 8) * 4);
            #pragma unroll
            for (int i = 0; i < 4; i++) {
                #pragma unroll
                for (int j = 0; j < 4; j++)
                    mma_tf32(acc[i][j], a[i], &b[j >> 1][(j & 1) * 2]);
            }
        }
        __syncthreads();
        if (c + GSTG - 1 < NC) issue(c + GSTG - 1);
    }

    #pragma unroll
    for (int j = 0; j < 4; j++) {
        const int col = n0 + wn * 32 + j * 8 + tig * 2;
        const float2 bz = *(const float2*)&bias[col];
        #pragma unroll
        for (int i = 0; i < 4; i++) {
            const int r0 = m0 + wm * 64 + i * 16 + gid;
            float2 o0, o1;
            o0.x = acc[i][j][0] + bz.x;  o0.y = acc[i][j][1] + bz.y;
            o1.x = acc[i][j][2] + bz.x;  o1.y = acc[i][j][3] + bz.y;
            *(float2*)&C[(size_t)r0 * N + col]       = o0;
            *(float2*)&C[(size_t)(r0 + 8) * N + col] = o1;
        }
    }
}

// ---------------------------------------------------------------------------
// Prep: tf32 rounding + weight transpose
// ---------------------------------------------------------------------------
__global__ __launch_bounds__(256) void cvt_x_tf32(const float* __restrict__ in,
                                                  float* __restrict__ out, int n4)
{
    int i = blockIdx.x * 256 + threadIdx.x;
    if (i >= n4) return;
    float4 v = ((const float4*)in)[i];
    v.x = to_tf32(v.x); v.y = to_tf32(v.y); v.z = to_tf32(v.z); v.w = to_tf32(v.w);
    ((float4*)out)[i] = v;
}

__global__ __launch_bounds__(256) void transpose_tf32(const float* __restrict__ W,
                                                      float* __restrict__ Wt, int K, int N)
{
    __shared__ float t[32][33];
    const int nb = blockIdx.x * 32, kb = blockIdx.y * 32;
    const int x = threadIdx.x & 31, y4 = (threadIdx.x >> 5) * 4;
    #pragma unroll
    for (int i = 0; i < 4; i++) t[y4 + i][x] = W[(size_t)(kb + y4 + i) * N + nb + x];
    __syncthreads();
    #pragma unroll
    for (int i = 0; i < 4; i++)
        Wt[(size_t)(nb + y4 + i) * K + kb + x] = to_tf32(t[x][y4 + i]);
}

// ---------------------------------------------------------------------------
// RMSNorm q/k heads in place; outputs tf32-rounded (feed tensor-core attn)
// ---------------------------------------------------------------------------
__global__ __launch_bounds__(256) void rmsnorm_qk(
    float* __restrict__ qkv, const float* __restrict__ q_scale, const float* __restrict__ k_scale)
{
    const int gw   = (blockIdx.x * blockDim.x + threadIdx.x) >> 5;
    const int lane = threadIdx.x & 31;
    const int token = gw / 20;
    const int slot  = gw % 20;
    if (token >= TOKENS) return;

    int col; const float* sc;
    if (slot < 16) { col = slot * HD;                  sc = q_scale; }
    else           { col = D_MODEL + (slot - 16) * HD; sc = k_scale; }

    float* p = qkv + (size_t)token * QKVW + col + lane * 4;
    float4 v = *(float4*)p;
    float ss = v.x * v.x + v.y * v.y + v.z * v.z + v.w * v.w;
    #pragma unroll
    for (int o = 16; o; o >>= 1) ss += __shfl_xor_sync(0xffffffffu, ss, o);
    const float r = rsqrtf(ss * (1.0f / HD) + 1e-6f);
    const float4 s4 = *(const float4*)(sc + lane * 4);
    v.x = to_tf32(v.x * r * s4.x);
    v.y = to_tf32(v.y * r * s4.y);
    v.z = to_tf32(v.z * r * s4.z);
    v.w = to_tf32(v.w * r * s4.w);
    *(float4*)p = v;
}

// ---------------------------------------------------------------------------
// Tensor-core causal flash attention (tf32 mma, fp32 softmax).
// BQ=128/CTA, BK=64. 8 warps, each owns 16 q-rows. Q,K row-major smem
// (stride 132), V^T and P stride 68. P routed via smem (warp-private rows).
// ---------------------------------------------------------------------------
#define QS_S 132
#define KS_S 132
#define VT_S 68
#define PS_S 68
#define FA_SMEM ((128*QS_S + 64*KS_S + 128*VT_S + 128*PS_S) * 4)

__global__ __launch_bounds__(256) void flash_attn_tc(
    const float* __restrict__ qkv, float* __restrict__ out)
{
    extern __shared__ __align__(16) float sm[];
    float* Qs = sm;                       // [128][132]
    float* Ks = Qs + 128 * QS_S;          // [64][132]
    float* Vt = Ks + 64 * KS_S;           // [128][68]  (V^T: n-major, k contiguous)
    float* Ps = Vt + 128 * VT_S;          // [128][68]  (P; also V row-major staging)

    const int qb = blockIdx.x, h = blockIdx.y, n = blockIdx.z;
    const int kvh = h >> 2;
    const int q0 = qb * 128;
    const int tid = threadIdx.x, wid = tid >> 5, lane = tid & 31;
    const int gid = lane >> 2, tig = lane & 3;

    const float* base = qkv + (size_t)n * SEQ * QKVW;
    const int qcol = h * HD;
    const int kcol = D_MODEL + kvh * HD;
    const int vcol = D_MODEL + KV_DIM + kvh * HD;

    // Load Q tile [128][128] row-major (already tf32-rounded by rmsnorm)
    for (int i = tid * 4; i < 128 * HD; i += 1024) {
        const int r = i >> 7, c = i & 127;
        *(float4*)&Qs[r * QS_S + c] =
            *(const float4*)&base[(size_t)(q0 + r) * QKVW + qcol + c];
    }

    const int a_row = (lane & 7) + ((lane >> 3) & 1) * 8;
    const int a_col = (lane >> 4) * 4;
    const int b_row = (lane & 7) + ((lane >> 4) & 1) * 8;
    const int b_col = ((lane >> 3) & 1) * 4;

    const uint32_t sQ = smem_u32(Qs), sK = smem_u32(Ks);
    const uint32_t sV = smem_u32(Vt), sP = smem_u32(Ps);

    const uint32_t QA = sQ + ((wid * 16 + a_row) * QS_S + a_col) * 4;
    const uint32_t KB = sK + (b_row * KS_S + b_col) * 4;
    const uint32_t PA = sP + ((wid * 16 + a_row) * PS_S + a_col) * 4;
    const uint32_t VB = sV + (b_row * VT_S + b_col) * 4;

    float oacc[16][4];
    #pragma unroll
    for (int j = 0; j < 16; j++)
        #pragma unroll
        for (int t = 0; t < 4; t++) oacc[j][t] = 0.f;

    float m0 = -1e30f, m1 = -1e30f, l0 = 0.f, l1 = 0.f;
    const float scale = 0.08838834764831843f;
    const int row0 = q0 + wid * 16 + gid;
    const int row1 = row0 + 8;

    const int ntiles = qb * 2 + 2;
    for (int t = 0; t < ntiles; t++) {
        const int k0 = t * 64;
        __syncthreads();
        // Load K row-major -> Ks; V row-major -> Ps staging (both coalesced)
        for (int i = tid * 4; i < 64 * HD; i += 1024) {
            const int r = i >> 7, c = i & 127;
            const size_t ro = (size_t)(k0 + r) * QKVW;
            *(float4*)&Ks[r * KS_S + c] = *(const float4*)&base[ro + kcol + c];
            *(float4*)&Ps[r * KS_S + c] = *(const float4*)&base[ro + vcol + c];
        }
        __syncthreads();
        // Transpose staged V -> Vt (lane-contiguous k: conflict-free stores)
        for (int o = tid; o < 128 * 64; o += 256) {
            const int vn = o >> 6, vk = o & 63;
            Vt[vn * VT_S + vk] = to_tf32(Ps[vk * KS_S + vn]);
        }
        __syncthreads();

        // S = Q @ K^T : 8 n8-tiles x 16 k8-steps per warp
        float sacc[8][4];
        #pragma unroll
        for (int j = 0; j < 8; j++)
            #pragma unroll
            for (int tt = 0; tt < 4; tt++) sacc[j][tt] = 0.f;

        #pragma unroll
        for (int k8 = 0; k8 < 16; k8++) {
            uint32_t a[4], b[4][4];
            ldm_x4(a, QA + k8 * 32);
            #pragma unroll
            for (int nt = 0; nt < 4; nt++)
                ldm_x4(b[nt], KB + (nt * 16 * KS_S + k8 * 8) * 4);
            #pragma unroll
            for (int j = 0; j < 8; j++)
                mma_tf32(sacc[j], a, &b[j >> 1][(j & 1) * 2]);
        }

        // Scale + causal mask + row max (rows warp-local; reduce over tig lanes)
        float rm0 = -1e30f, rm1 = -1e30f;
        #pragma unroll
        for (int j = 0; j < 8; j++) {
            const int c0 = k0 + j * 8 + 2 * tig, c1 = c0 + 1;
            sacc[j][0] = (c0 <= row0) ? sacc[j][0] * scale : -1e30f;
            sacc[j][1] = (c1 <= row0) ? sacc[j][1] * scale : -1e30f;
            sacc[j][2] = (c0 <= row1) ? sacc[j][2] * scale : -1e30f;
            sacc[j][3] = (c1 <= row1) ? sacc[j][3] * scale : -1e30f;
            rm0 = fmaxf(rm0, fmaxf(sacc[j][0], sacc[j][1]));
            rm1 = fmaxf(rm1, fmaxf(sacc[j][2], sacc[j][3]));
        }
        rm0 = fmaxf(rm0, __shfl_xor_sync(0xffffffffu, rm0, 1));
        rm0 = fmaxf(rm0, __shfl_xor_sync(0xffffffffu, rm0, 2));
        rm1 = fmaxf(rm1, __shfl_xor_sync(0xffffffffu, rm1, 1));
        rm1 = fmaxf(rm1, __shfl_xor_sync(0xffffffffu, rm1, 2));

        const float mn0 = fmaxf(m0, rm0), mn1 = fmaxf(m1, rm1);
        const float cor0 = __expf(m0 - mn0), cor1 = __expf(m1 - mn1);
        m0 = mn0; m1 = mn1;

        float ps0 = 0.f, ps1 = 0.f;
        const int prow0 = wid * 16 + gid;
        #pragma unroll
        for (int j = 0; j < 8; j++) {
            const float p00 = __expf(sacc[j][0] - mn0);
            const float p01 = __expf(sacc[j][1] - mn0);
            const float p10 = __expf(sacc[j][2] - mn1);
            const float p11 = __expf(sacc[j][3] - mn1);
            ps0 += p00 + p01; ps1 += p10 + p11;
            const int pc = j * 8 + 2 * tig;
            *(float2*)&Ps[prow0 * PS_S + pc]       = make_float2(to_tf32(p00), to_tf32(p01));
            *(float2*)&Ps[(prow0 + 8) * PS_S + pc] = make_float2(to_tf32(p10), to_tf32(p11));
        }
        ps0 += __shfl_xor_sync(0xffffffffu, ps0, 1);
        ps0 += __shfl_xor_sync(0xffffffffu, ps0, 2);
        ps1 += __shfl_xor_sync(0xffffffffu, ps1, 1);
        ps1 += __shfl_xor_sync(0xffffffffu, ps1, 2);
        l0 = l0 * cor0 + ps0;
        l1 = l1 * cor1 + ps1;

        #pragma unroll
        for (int j = 0; j < 16; j++) {
            oacc[j][0] *= cor0; oacc[j][1] *= cor0;
            oacc[j][2] *= cor1; oacc[j][3] *= cor1;
        }
        __syncwarp();   // P rows are warp-private; make stores visible to ldmatrix

        // O += P @ V : 16 n8-tiles x 8 k8-steps per warp
        #pragma unroll
        for (int k8 = 0; k8 < 8; k8++) {
            uint32_t a[4];
            ldm_x4(a, PA + k8 * 32);
            #pragma unroll
            for (int nt = 0; nt < 8; nt++) {
                uint32_t b[4];
                ldm_x4(b, VB + (nt * 16 * VT_S + k8 * 8) * 4);
                mma_tf32(oacc[2 * nt],     a, &b[0]);
                mma_tf32(oacc[2 * nt + 1], a, &b[2]);
            }
        }
    }

    // Epilogue: normalize, round to tf32 (feeds out-proj), store
    const float i0 = 1.f / l0, i1 = 1.f / l1;
    float* op0 = out + (size_t)(n * SEQ + row0) * D_MODEL + h * HD;
    float* op1 = out + (size_t)(n * SEQ + row1) * D_MODEL + h * HD;
    #pragma unroll
    for (int j = 0; j < 16; j++) {
        const int c = j * 8 + 2 * tig;
        *(float2*)&op0[c] = make_float2(to_tf32(oacc[j][0] * i0), to_tf32(oacc[j][1] * i0));
        *(float2*)&op1[c] = make_float2(to_tf32(oacc[j][2] * i1), to_tf32(oacc[j][3] * i1));
    }
}

// ---------------------------------------------------------------------------
extern "C" void kernel_launch(void* const* d_in, const int* in_sizes, int n_in,
                              void* d_out, int out_size)
{
    const float* x       = (const float*)d_in[0];
    const float* Wqkv    = (const float*)d_in[1];
    const float* bqkv    = (const float*)d_in[2];
    const float* q_scale = (const float*)d_in[3];
    const float* k_scale = (const float*)d_in[4];
    const float* Wout    = (const float*)d_in[5];
    const float* bout    = (const float*)d_in[6];
    float* out = (float*)d_out;

    float *qkv, *attn, *xc, *wqT, *woT;
    cudaGetSymbolAddress((void**)&qkv,  g_qkv);
    cudaGetSymbolAddress((void**)&attn, g_attn);
    cudaGetSymbolAddress((void**)&xc,   g_xc);
    cudaGetSymbolAddress((void**)&wqT,  g_wqkvT);
    cudaGetSymbolAddress((void**)&woT,  g_woutT);

    // Prep: tf32-round x, transpose+round weights
    cvt_x_tf32<<<(TOKENS * D_MODEL / 4 + 255) / 256, 256>>>(x, xc, TOKENS * D_MODEL / 4);
    transpose_tf32<<<dim3(QKVW / 32, KDIM / 32), 256>>>(Wqkv, wqT, KDIM, QKVW);
    transpose_tf32<<<dim3(D_MODEL / 32, KDIM / 32), 256>>>(Wout, woT, KDIM, D_MODEL);

    const int gsmem = GSTG * STAGE_F * 2 * (int)sizeof(float);
    cudaFuncSetAttribute(gemm_mma, cudaFuncAttributeMaxDynamicSharedMemorySize, gsmem);

    // 1) QKV projection (tensor-core tf32)
    gemm_mma<<<dim3(QKVW / 128, TOKENS / 128), 256, gsmem>>>(xc, wqT, bqkv, qkv, QKVW, KDIM);

    // 2) RMSNorm q/k heads (rounds outputs to tf32)
    rmsnorm_qk<<<(TOKENS * 20) / 8, 256>>>(qkv, q_scale, k_scale);

    // 3) Tensor-core causal flash attention
    cudaFuncSetAttribute(flash_attn_tc, cudaFuncAttributeMaxDynamicSharedMemorySize, FA_SMEM);
    flash_attn_tc<<<dim3(SEQ / 128, NH, NB), 256, FA_SMEM>>>(qkv, attn);

    // 4) Output projection (tensor-core tf32)
    gemm_mma<<<dim3(D_MODEL / 128, TOKENS / 128), 256, gsmem>>>(attn, woT, bout, out, D_MODEL, KDIM);
}

// round 5
// speedup vs baseline: 4.4039x; 1.0080x over previous
#include <cuda_runtime.h>
#include <math.h>
#include <stdint.h>

#define D_MODEL 2048
#define NH      16
#define NKV     4
#define HD      128
#define KV_DIM  512
#define QKVW    3072
#define NB      4
#define SEQ     2048
#define TOKENS  (NB * SEQ)
#define KDIM    2048

// Scratch (device globals — no runtime allocation)
__device__ float g_qkv  [(size_t)TOKENS * QKVW];
__device__ float g_attn [(size_t)TOKENS * D_MODEL];
__device__ float g_wqkvT[(size_t)QKVW   * D_MODEL];
__device__ float g_woutT[(size_t)D_MODEL* D_MODEL];

// ---------------------------------------------------------------------------
// Helpers (base-target PTX only: mma.sync / ldmatrix / cp.async / cvt.tf32)
// ---------------------------------------------------------------------------
__device__ __forceinline__ uint32_t smem_u32(const void* p) {
    uint32_t r;
    asm("{ .reg .u64 t; cvta.to.shared.u64 t, %1; cvt.u32.u64 %0, t; }" : "=r"(r) : "l"(p));
    return r;
}
__device__ __forceinline__ void cp16(uint32_t d, const void* s) {
    asm volatile("cp.async.cg.shared.global [%0], [%1], 16;" :: "r"(d), "l"(s));
}
__device__ __forceinline__ void cp_commit() {
    asm volatile("cp.async.commit_group;" ::: "memory");
}
template<int N> __device__ __forceinline__ void cp_wait() {
    asm volatile("cp.async.wait_group %0;" :: "n"(N) : "memory");
}
__device__ __forceinline__ void ldm_x4(uint32_t* r, uint32_t addr) {
    asm volatile("ldmatrix.sync.aligned.m8n8.x4.shared.b16 {%0,%1,%2,%3}, [%4];"
        : "=r"(r[0]), "=r"(r[1]), "=r"(r[2]), "=r"(r[3]) : "r"(addr));
}
__device__ __forceinline__ void mma_tf32(float* c, const uint32_t* a, const uint32_t* b) {
    asm volatile(
        "mma.sync.aligned.m16n8k8.row.col.f32.tf32.tf32.f32 "
        "{%0,%1,%2,%3}, {%4,%5,%6,%7}, {%8,%9}, {%0,%1,%2,%3};"
        : "+f"(c[0]), "+f"(c[1]), "+f"(c[2]), "+f"(c[3])
        : "r"(a[0]), "r"(a[1]), "r"(a[2]), "r"(a[3]), "r"(b[0]), "r"(b[1]));
}
__device__ __forceinline__ float to_tf32(float v) {
    uint32_t u;
    asm("cvt.rna.tf32.f32 %0, %1;" : "=r"(u) : "f"(v));
    return __uint_as_float(u);
}
__device__ __forceinline__ void rnd_frag4(uint32_t* r) {
    #pragma unroll
    for (int i = 0; i < 4; i++) {
        float f = __uint_as_float(r[i]);
        asm("cvt.rna.tf32.f32 %0, %1;" : "=r"(r[i]) : "f"(f));
    }
}

// ---------------------------------------------------------------------------
// TF32 tensor-core GEMM: C = A @ Bt^T + bias. A raw f32 (rounded in-register),
// Bt pre-rounded. Single-sync pipelined loop, issue at loop top.
// ---------------------------------------------------------------------------
#define BKG  32
#define GSTG 3
#define LDA  36
#define STAGE_F (128 * LDA)

__global__ __launch_bounds__(256) void gemm_mma(
    const float* __restrict__ A, const float* __restrict__ Bt,
    const float* __restrict__ bias, float* __restrict__ C,
    int N, int K)
{
    extern __shared__ __align__(16) float sh[];
    float* As = sh;
    float* Bs = sh + GSTG * STAGE_F;

    const int tid  = threadIdx.x;
    const int wid  = tid >> 5, lane = tid & 31;
    const int wm   = wid >> 2, wn = wid & 3;
    const int gid  = lane >> 2, tig = lane & 3;
    const int m0   = blockIdx.y * 128, n0 = blockIdx.x * 128;
    const int NC   = K / BKG;

    const uint32_t sA = smem_u32(As);
    const uint32_t sB = smem_u32(Bs);

    const int a_row = (lane & 7) + ((lane >> 3) & 1) * 8;
    const int a_col = (lane >> 4) * 4;
    const int b_row = (lane & 7) + ((lane >> 4) & 1) * 8;
    const int b_col = ((lane >> 3) & 1) * 4;

    float acc[4][4][4];
    #pragma unroll
    for (int i = 0; i < 4; i++)
        #pragma unroll
        for (int j = 0; j < 4; j++)
            #pragma unroll
            for (int t = 0; t < 4; t++) acc[i][j][t] = 0.f;

    auto issue = [&](int c) {
        const int s = c % GSTG;
        const float* Ag = A  + (size_t)m0 * K + c * BKG;
        const float* Bg = Bt + (size_t)n0 * K + c * BKG;
        const uint32_t Ad = sA + s * STAGE_F * 4;
        const uint32_t Bd = sB + s * STAGE_F * 4;
        #pragma unroll
        for (int it = 0; it < 4; it++) {
            const int blk = tid + it * 256;
            const int row = blk >> 3, quad = blk & 7;
            cp16(Ad + (row * LDA + quad * 4) * 4, Ag + (size_t)row * K + quad * 4);
            cp16(Bd + (row * LDA + quad * 4) * 4, Bg + (size_t)row * K + quad * 4);
        }
        cp_commit();
    };

    issue(0);
    issue(1);

    for (int c = 0; c < NC; c++) {
        if (c + 1 >= NC) cp_wait<0>(); else cp_wait<1>();
        __syncthreads();
        if (c + 2 < NC) issue(c + 2);   // overlaps with compute below

        const int s = c % GSTG;
        const uint32_t Abase = sA + (s * STAGE_F + (wm * 64 + a_row) * LDA + a_col) * 4;
        const uint32_t Bbase = sB + (s * STAGE_F + (wn * 32 + b_row) * LDA + b_col) * 4;

        #pragma unroll
        for (int k8 = 0; k8 < 4; k8++) {
            uint32_t a[4][4], b[2][4];
            #pragma unroll
            for (int i = 0; i < 4; i++) {
                ldm_x4(a[i], Abase + (i * 16 * LDA + k8 * 8) * 4);
                rnd_frag4(a[i]);        // A rounded to tf32 in-register
            }
            #pragma unroll
            for (int j2 = 0; j2 < 2; j2++)
                ldm_x4(b[j2], Bbase + (j2 * 16 * LDA + k8 * 8) * 4);
            #pragma unroll
            for (int i = 0; i < 4; i++) {
                #pragma unroll
                for (int j = 0; j < 4; j++)
                    mma_tf32(acc[i][j], a[i], &b[j >> 1][(j & 1) * 2]);
            }
        }
    }

    #pragma unroll
    for (int j = 0; j < 4; j++) {
        const int col = n0 + wn * 32 + j * 8 + tig * 2;
        const float2 bz = *(const float2*)&bias[col];
        #pragma unroll
        for (int i = 0; i < 4; i++) {
            const int r0 = m0 + wm * 64 + i * 16 + gid;
            float2 o0, o1;
            o0.x = acc[i][j][0] + bz.x;  o0.y = acc[i][j][1] + bz.y;
            o1.x = acc[i][j][2] + bz.x;  o1.y = acc[i][j][3] + bz.y;
            *(float2*)&C[(size_t)r0 * N + col]       = o0;
            *(float2*)&C[(size_t)(r0 + 8) * N + col] = o1;
        }
    }
}

// ---------------------------------------------------------------------------
// Weight transpose + tf32 round (-> K-major Bt)
// ---------------------------------------------------------------------------
__global__ __launch_bounds__(256) void transpose_tf32(const float* __restrict__ W,
                                                      float* __restrict__ Wt, int K, int N)
{
    __shared__ float t[32][33];
    const int nb = blockIdx.x * 32, kb = blockIdx.y * 32;
    const int x = threadIdx.x & 31, y4 = (threadIdx.x >> 5) * 4;
    #pragma unroll
    for (int i = 0; i < 4; i++) t[y4 + i][x] = W[(size_t)(kb + y4 + i) * N + nb + x];
    __syncthreads();
    #pragma unroll
    for (int i = 0; i < 4; i++)
        Wt[(size_t)(nb + y4 + i) * K + kb + x] = to_tf32(t[x][y4 + i]);
}

// ---------------------------------------------------------------------------
// RMSNorm q/k heads in place; outputs tf32-rounded
// ---------------------------------------------------------------------------
__global__ __launch_bounds__(256) void rmsnorm_qk(
    float* __restrict__ qkv, const float* __restrict__ q_scale, const float* __restrict__ k_scale)
{
    const int gw   = (blockIdx.x * blockDim.x + threadIdx.x) >> 5;
    const int lane = threadIdx.x & 31;
    const int token = gw / 20;
    const int slot  = gw % 20;
    if (token >= TOKENS) return;

    int col; const float* sc;
    if (slot < 16) { col = slot * HD;                  sc = q_scale; }
    else           { col = D_MODEL + (slot - 16) * HD; sc = k_scale; }

    float* p = qkv + (size_t)token * QKVW + col + lane * 4;
    float4 v = *(float4*)p;
    float ss = v.x * v.x + v.y * v.y + v.z * v.z + v.w * v.w;
    #pragma unroll
    for (int o = 16; o; o >>= 1) ss += __shfl_xor_sync(0xffffffffu, ss, o);
    const float r = rsqrtf(ss * (1.0f / HD) + 1e-6f);
    const float4 s4 = *(const float4*)(sc + lane * 4);
    v.x = to_tf32(v.x * r * s4.x);
    v.y = to_tf32(v.y * r * s4.y);
    v.z = to_tf32(v.z * r * s4.z);
    v.w = to_tf32(v.w * r * s4.w);
    *(float4*)p = v;
}

// ---------------------------------------------------------------------------
// Tensor-core causal flash attention with cp.async K/V prefetch.
// BQ=128/CTA, BK=64. Separate Vrow staging buffer; next K+V tile issued
// after S phase, overlapping softmax + PV. 2 barriers/tile.
// ---------------------------------------------------------------------------
#define QS_S 132
#define KS_S 132
#define VT_S 68
#define PS_S 68
#define FA_SMEM ((128*QS_S + 64*KS_S + 64*KS_S + 128*VT_S + 128*PS_S) * 4)

__global__ __launch_bounds__(256) void flash_attn_tc(
    const float* __restrict__ qkv, float* __restrict__ out)
{
    extern __shared__ __align__(16) float sm[];
    float* Qs = sm;                       // [128][132]
    float* Ks = Qs + 128 * QS_S;          // [64][132]
    float* Vr = Ks + 64 * KS_S;           // [64][132]  V row-major staging
    float* Vt = Vr + 64 * KS_S;           // [128][68]  V^T
    float* Ps = Vt + 128 * VT_S;          // [128][68]  P

    const int qb = gridDim.x - 1 - blockIdx.x;   // longest CTAs first
    const int h = blockIdx.y, n = blockIdx.z;
    const int kvh = h >> 2;
    const int q0 = qb * 128;
    const int tid = threadIdx.x, wid = tid >> 5, lane = tid & 31;
    const int gid = lane >> 2, tig = lane & 3;

    const float* base = qkv + (size_t)n * SEQ * QKVW;
    const int qcol = h * HD;
    const int kcol = D_MODEL + kvh * HD;
    const int vcol = D_MODEL + KV_DIM + kvh * HD;

    const uint32_t sQ = smem_u32(Qs), sK = smem_u32(Ks);
    const uint32_t sVr = smem_u32(Vr), sV = smem_u32(Vt), sP = smem_u32(Ps);

    const int ntiles = qb * 2 + 2;

    // cp.async loader for K+V of tile t (one commit group)
    auto loadKV = [&](int t) {
        const int k0 = t * 64;
        #pragma unroll
        for (int it = 0; it < 8; it++) {
            const int i = (tid + it * 256) * 4;      // 0..8188
            const int r = i >> 7, c = i & 127;
            const size_t ro = (size_t)(k0 + r) * QKVW;
            cp16(sK  + (r * KS_S + c) * 4, &base[ro + kcol + c]);
            cp16(sVr + (r * KS_S + c) * 4, &base[ro + vcol + c]);
        }
        cp_commit();
    };

    loadKV(0);

    // Load Q tile [128][128] row-major (tf32-rounded already)
    for (int i = tid * 4; i < 128 * HD; i += 1024) {
        const int r = i >> 7, c = i & 127;
        *(float4*)&Qs[r * QS_S + c] =
            *(const float4*)&base[(size_t)(q0 + r) * QKVW + qcol + c];
    }

    const int a_row = (lane & 7) + ((lane >> 3) & 1) * 8;
    const int a_col = (lane >> 4) * 4;
    const int b_row = (lane & 7) + ((lane >> 4) & 1) * 8;
    const int b_col = ((lane >> 3) & 1) * 4;

    const uint32_t QA = sQ + ((wid * 16 + a_row) * QS_S + a_col) * 4;
    const uint32_t KB = sK + (b_row * KS_S + b_col) * 4;
    const uint32_t PA = sP + ((wid * 16 + a_row) * PS_S + a_col) * 4;
    const uint32_t VB = sV + (b_row * VT_S + b_col) * 4;

    float oacc[16][4];
    #pragma unroll
    for (int j = 0; j < 16; j++)
        #pragma unroll
        for (int t = 0; t < 4; t++) oacc[j][t] = 0.f;

    float m0 = -1e30f, m1 = -1e30f, l0 = 0.f, l1 = 0.f;
    const float scale = 0.08838834764831843f;
    const int row0 = q0 + wid * 16 + gid;
    const int row1 = row0 + 8;

    for (int t = 0; t < ntiles; t++) {
        const int k0 = t * 64;
        cp_wait<0>();          // KV(t) landed
        __syncthreads();       // + Vt/Ks free (prev PV/S done), KV visible to all

        // Transpose staged V -> Vt (round to tf32)
        for (int o = tid; o < 128 * 64; o += 256) {
            const int vn = o >> 6, vk = o & 63;
            Vt[vn * VT_S + vk] = to_tf32(Vr[vk * KS_S + vn]);
        }

        // S = Q @ K^T : 8 n8-tiles x 16 k8-steps per warp
        float sacc[8][4];
        #pragma unroll
        for (int j = 0; j < 8; j++)
            #pragma unroll
            for (int tt = 0; tt < 4; tt++) sacc[j][tt] = 0.f;

        #pragma unroll
        for (int k8 = 0; k8 < 16; k8++) {
            uint32_t a[4], b[4][4];
            ldm_x4(a, QA + k8 * 32);
            #pragma unroll
            for (int nt = 0; nt < 4; nt++)
                ldm_x4(b[nt], KB + (nt * 16 * KS_S + k8 * 8) * 4);
            #pragma unroll
            for (int j = 0; j < 8; j++)
                mma_tf32(sacc[j], a, &b[j >> 1][(j & 1) * 2]);
        }

        __syncthreads();                        // transpose done; Ks, Vr free
        if (t + 1 < ntiles) loadKV(t + 1);      // overlaps softmax + PV

        // Scale + causal mask + row max
        float rm0 = -1e30f, rm1 = -1e30f;
        #pragma unroll
        for (int j = 0; j < 8; j++) {
            const int c0 = k0 + j * 8 + 2 * tig, c1 = c0 + 1;
            sacc[j][0] = (c0 <= row0) ? sacc[j][0] * scale : -1e30f;
            sacc[j][1] = (c1 <= row0) ? sacc[j][1] * scale : -1e30f;
            sacc[j][2] = (c0 <= row1) ? sacc[j][2] * scale : -1e30f;
            sacc[j][3] = (c1 <= row1) ? sacc[j][3] * scale : -1e30f;
            rm0 = fmaxf(rm0, fmaxf(sacc[j][0], sacc[j][1]));
            rm1 = fmaxf(rm1, fmaxf(sacc[j][2], sacc[j][3]));
        }
        rm0 = fmaxf(rm0, __shfl_xor_sync(0xffffffffu, rm0, 1));
        rm0 = fmaxf(rm0, __shfl_xor_sync(0xffffffffu, rm0, 2));
        rm1 = fmaxf(rm1, __shfl_xor_sync(0xffffffffu, rm1, 1));
        rm1 = fmaxf(rm1, __shfl_xor_sync(0xffffffffu, rm1, 2));

        const float mn0 = fmaxf(m0, rm0), mn1 = fmaxf(m1, rm1);
        const float cor0 = __expf(m0 - mn0), cor1 = __expf(m1 - mn1);
        m0 = mn0; m1 = mn1;

        float ps0 = 0.f, ps1 = 0.f;
        const int prow0 = wid * 16 + gid;
        #pragma unroll
        for (int j = 0; j < 8; j++) {
            const float p00 = __expf(sacc[j][0] - mn0);
            const float p01 = __expf(sacc[j][1] - mn0);
            const float p10 = __expf(sacc[j][2] - mn1);
            const float p11 = __expf(sacc[j][3] - mn1);
            ps0 += p00 + p01; ps1 += p10 + p11;
            const int pc = j * 8 + 2 * tig;
            *(float2*)&Ps[prow0 * PS_S + pc]       = make_float2(to_tf32(p00), to_tf32(p01));
            *(float2*)&Ps[(prow0 + 8) * PS_S + pc] = make_float2(to_tf32(p10), to_tf32(p11));
        }
        ps0 += __shfl_xor_sync(0xffffffffu, ps0, 1);
        ps0 += __shfl_xor_sync(0xffffffffu, ps0, 2);
        ps1 += __shfl_xor_sync(0xffffffffu, ps1, 1);
        ps1 += __shfl_xor_sync(0xffffffffu, ps1, 2);
        l0 = l0 * cor0 + ps0;
        l1 = l1 * cor1 + ps1;

        #pragma unroll
        for (int j = 0; j < 16; j++) {
            oacc[j][0] *= cor0; oacc[j][1] *= cor0;
            oacc[j][2] *= cor1; oacc[j][3] *= cor1;
        }
        __syncwarp();   // P rows are warp-private

        // O += P @ V : 16 n8-tiles x 8 k8-steps per warp
        #pragma unroll
        for (int k8 = 0; k8 < 8; k8++) {
            uint32_t a[4];
            ldm_x4(a, PA + k8 * 32);
            #pragma unroll
            for (int nt = 0; nt < 8; nt++) {
                uint32_t b[4];
                ldm_x4(b, VB + (nt * 16 * VT_S + k8 * 8) * 4);
                mma_tf32(oacc[2 * nt],     a, &b[0]);
                mma_tf32(oacc[2 * nt + 1], a, &b[2]);
            }
        }
    }

    // Epilogue: normalize, round to tf32 (feeds out-proj), store
    const float i0 = 1.f / l0, i1 = 1.f / l1;
    float* op0 = out + (size_t)(n * SEQ + row0) * D_MODEL + h * HD;
    float* op1 = out + (size_t)(n * SEQ + row1) * D_MODEL + h * HD;
    #pragma unroll
    for (int j = 0; j < 16; j++) {
        const int c = j * 8 + 2 * tig;
        *(float2*)&op0[c] = make_float2(to_tf32(oacc[j][0] * i0), to_tf32(oacc[j][1] * i0));
        *(float2*)&op1[c] = make_float2(to_tf32(oacc[j][2] * i1), to_tf32(oacc[j][3] * i1));
    }
}

// ---------------------------------------------------------------------------
extern "C" void kernel_launch(void* const* d_in, const int* in_sizes, int n_in,
                              void* d_out, int out_size)
{
    const float* x       = (const float*)d_in[0];
    const float* Wqkv    = (const float*)d_in[1];
    const float* bqkv    = (const float*)d_in[2];
    const float* q_scale = (const float*)d_in[3];
    const float* k_scale = (const float*)d_in[4];
    const float* Wout    = (const float*)d_in[5];
    const float* bout    = (const float*)d_in[6];
    float* out = (float*)d_out;

    float *qkv, *attn, *wqT, *woT;
    cudaGetSymbolAddress((void**)&qkv,  g_qkv);
    cudaGetSymbolAddress((void**)&attn, g_attn);
    cudaGetSymbolAddress((void**)&wqT,  g_wqkvT);
    cudaGetSymbolAddress((void**)&woT,  g_woutT);

    // Prep: transpose+round weights (x rounded in-register inside gemm)
    transpose_tf32<<<dim3(QKVW / 32, KDIM / 32), 256>>>(Wqkv, wqT, KDIM, QKVW);
    transpose_tf32<<<dim3(D_MODEL / 32, KDIM / 32), 256>>>(Wout, woT, KDIM, D_MODEL);

    const int gsmem = GSTG * STAGE_F * 2 * (int)sizeof(float);
    cudaFuncSetAttribute(gemm_mma, cudaFuncAttributeMaxDynamicSharedMemorySize, gsmem);

    // 1) QKV projection (tensor-core tf32)
    gemm_mma<<<dim3(QKVW / 128, TOKENS / 128), 256, gsmem>>>(x, wqT, bqkv, qkv, QKVW, KDIM);

    // 2) RMSNorm q/k heads (rounds outputs to tf32)
    rmsnorm_qk<<<(TOKENS * 20) / 8, 256>>>(qkv, q_scale, k_scale);

    // 3) Tensor-core causal flash attention (cp.async prefetch)
    cudaFuncSetAttribute(flash_attn_tc, cudaFuncAttributeMaxDynamicSharedMemorySize, FA_SMEM);
    flash_attn_tc<<<dim3(SEQ / 128, NH, NB), 256, FA_SMEM>>>(qkv, attn);

    // 4) Output projection (tensor-core tf32)
    gemm_mma<<<dim3(D_MODEL / 128, TOKENS / 128), 256, gsmem>>>(attn, woT, bout, out, D_MODEL, KDIM);
}

// round 6
// speedup vs baseline: 4.5063x; 1.0233x over previous
#include <cuda_runtime.h>
#include <math.h>
#include <stdint.h>

#define D_MODEL 2048
#define NH      16
#define NKV     4
#define HD      128
#define KV_DIM  512
#define QKVW    3072
#define NB      4
#define SEQ     2048
#define TOKENS  (NB * SEQ)
#define KDIM    2048

// Scratch (device globals — no runtime allocation)
__device__ float g_qkv  [(size_t)TOKENS * QKVW];
__device__ float g_attn [(size_t)TOKENS * D_MODEL];
__device__ float g_wqkvT[(size_t)QKVW   * D_MODEL];
__device__ float g_woutT[(size_t)D_MODEL* D_MODEL];

// ---------------------------------------------------------------------------
// Helpers (base-target PTX only)
// ---------------------------------------------------------------------------
__device__ __forceinline__ uint32_t smem_u32(const void* p) {
    uint32_t r;
    asm("{ .reg .u64 t; cvta.to.shared.u64 t, %1; cvt.u32.u64 %0, t; }" : "=r"(r) : "l"(p));
    return r;
}
__device__ __forceinline__ void cp16(uint32_t d, const void* s) {
    asm volatile("cp.async.cg.shared.global [%0], [%1], 16;" :: "r"(d), "l"(s));
}
__device__ __forceinline__ void cp_commit() {
    asm volatile("cp.async.commit_group;" ::: "memory");
}
template<int N> __device__ __forceinline__ void cp_wait() {
    asm volatile("cp.async.wait_group %0;" :: "n"(N) : "memory");
}
__device__ __forceinline__ void ldm_x4(uint32_t* r, uint32_t addr) {
    asm volatile("ldmatrix.sync.aligned.m8n8.x4.shared.b16 {%0,%1,%2,%3}, [%4];"
        : "=r"(r[0]), "=r"(r[1]), "=r"(r[2]), "=r"(r[3]) : "r"(addr));
}
__device__ __forceinline__ void mma_tf32(float* c, const uint32_t* a, const uint32_t* b) {
    asm volatile(
        "mma.sync.aligned.m16n8k8.row.col.f32.tf32.tf32.f32 "
        "{%0,%1,%2,%3}, {%4,%5,%6,%7}, {%8,%9}, {%0,%1,%2,%3};"
        : "+f"(c[0]), "+f"(c[1]), "+f"(c[2]), "+f"(c[3])
        : "r"(a[0]), "r"(a[1]), "r"(a[2]), "r"(a[3]), "r"(b[0]), "r"(b[1]));
}
__device__ __forceinline__ float to_tf32(float v) {
    uint32_t u;
    asm("cvt.rna.tf32.f32 %0, %1;" : "=r"(u) : "f"(v));
    return __uint_as_float(u);
}
__device__ __forceinline__ void rnd_frag4(uint32_t* r) {
    #pragma unroll
    for (int i = 0; i < 4; i++) {
        float f = __uint_as_float(r[i]);
        asm("cvt.rna.tf32.f32 %0, %1;" : "=r"(r[i]) : "f"(f));
    }
}

// ---------------------------------------------------------------------------
// TF32 tensor-core GEMM (unchanged from R5): C = A @ Bt^T + bias
// ---------------------------------------------------------------------------
#define BKG  32
#define GSTG 3
#define LDA  36
#define STAGE_F (128 * LDA)

__global__ __launch_bounds__(256) void gemm_mma(
    const float* __restrict__ A, const float* __restrict__ Bt,
    const float* __restrict__ bias, float* __restrict__ C,
    int N, int K)
{
    extern __shared__ __align__(16) float sh[];
    float* As = sh;
    float* Bs = sh + GSTG * STAGE_F;

    const int tid  = threadIdx.x;
    const int wid  = tid >> 5, lane = tid & 31;
    const int wm   = wid >> 2, wn = wid & 3;
    const int gid  = lane >> 2, tig = lane & 3;
    const int m0   = blockIdx.y * 128, n0 = blockIdx.x * 128;
    const int NC   = K / BKG;

    const uint32_t sA = smem_u32(As);
    const uint32_t sB = smem_u32(Bs);

    const int a_row = (lane & 7) + ((lane >> 3) & 1) * 8;
    const int a_col = (lane >> 4) * 4;
    const int b_row = (lane & 7) + ((lane >> 4) & 1) * 8;
    const int b_col = ((lane >> 3) & 1) * 4;

    float acc[4][4][4];
    #pragma unroll
    for (int i = 0; i < 4; i++)
        #pragma unroll
        for (int j = 0; j < 4; j++)
            #pragma unroll
            for (int t = 0; t < 4; t++) acc[i][j][t] = 0.f;

    auto issue = [&](int c) {
        const int s = c % GSTG;
        const float* Ag = A  + (size_t)m0 * K + c * BKG;
        const float* Bg = Bt + (size_t)n0 * K + c * BKG;
        const uint32_t Ad = sA + s * STAGE_F * 4;
        const uint32_t Bd = sB + s * STAGE_F * 4;
        #pragma unroll
        for (int it = 0; it < 4; it++) {
            const int blk = tid + it * 256;
            const int row = blk >> 3, quad = blk & 7;
            cp16(Ad + (row * LDA + quad * 4) * 4, Ag + (size_t)row * K + quad * 4);
            cp16(Bd + (row * LDA + quad * 4) * 4, Bg + (size_t)row * K + quad * 4);
        }
        cp_commit();
    };

    issue(0);
    issue(1);

    for (int c = 0; c < NC; c++) {
        if (c + 1 >= NC) cp_wait<0>(); else cp_wait<1>();
        __syncthreads();
        if (c + 2 < NC) issue(c + 2);

        const int s = c % GSTG;
        const uint32_t Abase = sA + (s * STAGE_F + (wm * 64 + a_row) * LDA + a_col) * 4;
        const uint32_t Bbase = sB + (s * STAGE_F + (wn * 32 + b_row) * LDA + b_col) * 4;

        #pragma unroll
        for (int k8 = 0; k8 < 4; k8++) {
            uint32_t a[4][4], b[2][4];
            #pragma unroll
            for (int i = 0; i < 4; i++) {
                ldm_x4(a[i], Abase + (i * 16 * LDA + k8 * 8) * 4);
                rnd_frag4(a[i]);
            }
            #pragma unroll
            for (int j2 = 0; j2 < 2; j2++)
                ldm_x4(b[j2], Bbase + (j2 * 16 * LDA + k8 * 8) * 4);
            #pragma unroll
            for (int i = 0; i < 4; i++) {
                #pragma unroll
                for (int j = 0; j < 4; j++)
                    mma_tf32(acc[i][j], a[i], &b[j >> 1][(j & 1) * 2]);
            }
        }
    }

    #pragma unroll
    for (int j = 0; j < 4; j++) {
        const int col = n0 + wn * 32 + j * 8 + tig * 2;
        const float2 bz = *(const float2*)&bias[col];
        #pragma unroll
        for (int i = 0; i < 4; i++) {
            const int r0 = m0 + wm * 64 + i * 16 + gid;
            float2 o0, o1;
            o0.x = acc[i][j][0] + bz.x;  o0.y = acc[i][j][1] + bz.y;
            o1.x = acc[i][j][2] + bz.x;  o1.y = acc[i][j][3] + bz.y;
            *(float2*)&C[(size_t)r0 * N + col]       = o0;
            *(float2*)&C[(size_t)(r0 + 8) * N + col] = o1;
        }
    }
}

// ---------------------------------------------------------------------------
// Weight transpose + tf32 round
// ---------------------------------------------------------------------------
__global__ __launch_bounds__(256) void transpose_tf32(const float* __restrict__ W,
                                                      float* __restrict__ Wt, int K, int N)
{
    __shared__ float t[32][33];
    const int nb = blockIdx.x * 32, kb = blockIdx.y * 32;
    const int x = threadIdx.x & 31, y4 = (threadIdx.x >> 5) * 4;
    #pragma unroll
    for (int i = 0; i < 4; i++) t[y4 + i][x] = W[(size_t)(kb + y4 + i) * N + nb + x];
    __syncthreads();
    #pragma unroll
    for (int i = 0; i < 4; i++)
        Wt[(size_t)(nb + y4 + i) * K + kb + x] = to_tf32(t[x][y4 + i]);
}

// ---------------------------------------------------------------------------
// RMSNorm q/k heads in place; outputs tf32-rounded
// ---------------------------------------------------------------------------
__global__ __launch_bounds__(256) void rmsnorm_qk(
    float* __restrict__ qkv, const float* __restrict__ q_scale, const float* __restrict__ k_scale)
{
    const int gw   = (blockIdx.x * blockDim.x + threadIdx.x) >> 5;
    const int lane = threadIdx.x & 31;
    const int token = gw / 20;
    const int slot  = gw % 20;
    if (token >= TOKENS) return;

    int col; const float* sc;
    if (slot < 16) { col = slot * HD;                  sc = q_scale; }
    else           { col = D_MODEL + (slot - 16) * HD; sc = k_scale; }

    float* p = qkv + (size_t)token * QKVW + col + lane * 4;
    float4 v = *(float4*)p;
    float ss = v.x * v.x + v.y * v.y + v.z * v.z + v.w * v.w;
    #pragma unroll
    for (int o = 16; o; o >>= 1) ss += __shfl_xor_sync(0xffffffffu, ss, o);
    const float r = rsqrtf(ss * (1.0f / HD) + 1e-6f);
    const float4 s4 = *(const float4*)(sc + lane * 4);
    v.x = to_tf32(v.x * r * s4.x);
    v.y = to_tf32(v.y * r * s4.y);
    v.z = to_tf32(v.z * r * s4.z);
    v.w = to_tf32(v.w * r * s4.w);
    *(float4*)p = v;
}

// ---------------------------------------------------------------------------
// Tensor-core causal flash attention — 512 threads / 16 warps per CTA.
// S phase: warp grid 8m x 2n (16 rows x 32 cols each).
// PV phase: warp grid 8m x 2d (16 rows x 64 d-cols each).
// Cross-warp row stats via smem reduction array. 3 barriers/tile.
// ---------------------------------------------------------------------------
#define QS_S 132
#define KS_S 132
#define VT_S 68
#define PS_S 68
#define FA_NT 512
// floats: Q + K + Vr + Vt + P + red(512)
#define FA_SMEM ((128*QS_S + 64*KS_S + 64*KS_S + 128*VT_S + 128*PS_S + 512) * 4)

__global__ __launch_bounds__(FA_NT) void flash_attn_tc(
    const float* __restrict__ qkv, float* __restrict__ out)
{
    extern __shared__ __align__(16) float sm[];
    float* Qs  = sm;                        // [128][132]
    float* Ks  = Qs + 128 * QS_S;           // [64][132]
    float* Vr  = Ks + 64 * KS_S;            // [64][132]  V row-major staging
    float* Vt  = Vr + 64 * KS_S;            // [128][68]  V^T
    float* Ps  = Vt + 128 * VT_S;           // [128][68]  P
    float* red = Ps + 128 * PS_S;           // [512]: max [128][2], sum [128][2]

    const int qb = gridDim.x - 1 - blockIdx.x;   // longest CTAs first
    const int h = blockIdx.y, n = blockIdx.z;
    const int kvh = h >> 2;
    const int q0 = qb * 128;
    const int tid = threadIdx.x, wid = tid >> 5, lane = tid & 31;
    const int gid = lane >> 2, tig = lane & 3;
    const int mw = wid & 7;          // m-block (16 rows)
    const int nh = wid >> 3;         // S: n-half (32 cols); PV: d-half (64 cols)

    const float* base = qkv + (size_t)n * SEQ * QKVW;
    const int qcol = h * HD;
    const int kcol = D_MODEL + kvh * HD;
    const int vcol = D_MODEL + KV_DIM + kvh * HD;

    const uint32_t sQ = smem_u32(Qs), sK = smem_u32(Ks);
    const uint32_t sVr = smem_u32(Vr), sV = smem_u32(Vt), sP = smem_u32(Ps);

    const int ntiles = qb * 2 + 2;

    auto loadKV = [&](int t) {
        const int k0 = t * 64;
        #pragma unroll
        for (int it = 0; it < 4; it++) {
            const int i = (tid + it * FA_NT) * 4;   // 0..8188
            const int r = i >> 7, c = i & 127;
            const size_t ro = (size_t)(k0 + r) * QKVW;
            cp16(sK  + (r * KS_S + c) * 4, &base[ro + kcol + c]);
            cp16(sVr + (r * KS_S + c) * 4, &base[ro + vcol + c]);
        }
        cp_commit();
    };

    loadKV(0);

    // Load Q tile [128][128] row-major (tf32-rounded already)
    for (int i = tid * 4; i < 128 * HD; i += FA_NT * 4) {
        const int r = i >> 7, c = i & 127;
        *(float4*)&Qs[r * QS_S + c] =
            *(const float4*)&base[(size_t)(q0 + r) * QKVW + qcol + c];
    }

    const int a_row = (lane & 7) + ((lane >> 3) & 1) * 8;
    const int a_col = (lane >> 4) * 4;
    const int b_row = (lane & 7) + ((lane >> 4) & 1) * 8;
    const int b_col = ((lane >> 3) & 1) * 4;

    const uint32_t QA = sQ + ((mw * 16 + a_row) * QS_S + a_col) * 4;
    const uint32_t KB = sK + ((nh * 32 + b_row) * KS_S + b_col) * 4;
    const uint32_t PA = sP + ((mw * 16 + a_row) * PS_S + a_col) * 4;
    const uint32_t VB = sV + ((nh * 64 + b_row) * VT_S + b_col) * 4;

    float oacc[8][4];
    #pragma unroll
    for (int j = 0; j < 8; j++)
        #pragma unroll
        for (int t = 0; t < 4; t++) oacc[j][t] = 0.f;

    float m0 = -1e30f, m1 = -1e30f, l0 = 0.f, l1 = 0.f;
    const float scale = 0.08838834764831843f;
    const int rrow0 = mw * 16 + gid;        // CTA-local row
    const int rrow1 = rrow0 + 8;
    const int row0 = q0 + rrow0, row1 = q0 + rrow1;

    for (int t = 0; t < ntiles; t++) {
        const int k0 = t * 64;
        cp_wait<0>();
        __syncthreads();    // KV(t) visible; Vt/P free (prev PV done everywhere)

        // Transpose staged V -> Vt. Lanes vary vk: STS conflict-free, LDS.128 4-way.
        #pragma unroll
        for (int it = 0; it < 4; it++) {
            const int o = tid + it * FA_NT;         // 0..2047
            const int vk = o & 63, vn4 = (o >> 6) & 31;
            const float4 v4 = *(const float4*)&Vr[vk * KS_S + vn4 * 4];
            Vt[(vn4 * 4 + 0) * VT_S + vk] = to_tf32(v4.x);
            Vt[(vn4 * 4 + 1) * VT_S + vk] = to_tf32(v4.y);
            Vt[(vn4 * 4 + 2) * VT_S + vk] = to_tf32(v4.z);
            Vt[(vn4 * 4 + 3) * VT_S + vk] = to_tf32(v4.w);
        }

        // S = Q @ K^T : warp = 16 rows x 32 cols; 4 n8 x 16 k8
        float sacc[4][4];
        #pragma unroll
        for (int j = 0; j < 4; j++)
            #pragma unroll
            for (int tt = 0; tt < 4; tt++) sacc[j][tt] = 0.f;

        #pragma unroll
        for (int k8 = 0; k8 < 16; k8++) {
            uint32_t a[4], b[2][4];
            ldm_x4(a, QA + k8 * 32);
            ldm_x4(b[0], KB + k8 * 32);
            ldm_x4(b[1], KB + (16 * KS_S + k8 * 8) * 4);
            #pragma unroll
            for (int j = 0; j < 4; j++)
                mma_tf32(sacc[j], a, &b[j >> 1][(j & 1) * 2]);
        }

        // Scale + causal mask + partial row max over this warp's 32 cols
        float rm0 = -1e30f, rm1 = -1e30f;
        #pragma unroll
        for (int j = 0; j < 4; j++) {
            const int c0 = k0 + nh * 32 + j * 8 + 2 * tig, c1 = c0 + 1;
            sacc[j][0] = (c0 <= row0) ? sacc[j][0] * scale : -1e30f;
            sacc[j][1] = (c1 <= row0) ? sacc[j][1] * scale : -1e30f;
            sacc[j][2] = (c0 <= row1) ? sacc[j][2] * scale : -1e30f;
            sacc[j][3] = (c1 <= row1) ? sacc[j][3] * scale : -1e30f;
            rm0 = fmaxf(rm0, fmaxf(sacc[j][0], sacc[j][1]));
            rm1 = fmaxf(rm1, fmaxf(sacc[j][2], sacc[j][3]));
        }
        rm0 = fmaxf(rm0, __shfl_xor_sync(0xffffffffu, rm0, 1));
        rm0 = fmaxf(rm0, __shfl_xor_sync(0xffffffffu, rm0, 2));
        rm1 = fmaxf(rm1, __shfl_xor_sync(0xffffffffu, rm1, 1));
        rm1 = fmaxf(rm1, __shfl_xor_sync(0xffffffffu, rm1, 2));
        if (tig == 0) {
            red[rrow0 * 2 + nh] = rm0;
            red[rrow1 * 2 + nh] = rm1;
        }

        __syncthreads();    // partial maxes visible; S reads of Ks + transpose done
        if (t + 1 < ntiles) loadKV(t + 1);   // overlaps softmax + PV

        const float mn0 = fmaxf(m0, fmaxf(red[rrow0 * 2], red[rrow0 * 2 + 1]));
        const float mn1 = fmaxf(m1, fmaxf(red[rrow1 * 2], red[rrow1 * 2 + 1]));
        const float cor0 = __expf(m0 - mn0), cor1 = __expf(m1 - mn1);
        m0 = mn0; m1 = mn1;

        float ps0 = 0.f, ps1 = 0.f;
        #pragma unroll
        for (int j = 0; j < 4; j++) {
            const float p00 = __expf(sacc[j][0] - mn0);
            const float p01 = __expf(sacc[j][1] - mn0);
            const float p10 = __expf(sacc[j][2] - mn1);
            const float p11 = __expf(sacc[j][3] - mn1);
            ps0 += p00 + p01; ps1 += p10 + p11;
            const int pc = nh * 32 + j * 8 + 2 * tig;
            *(float2*)&Ps[rrow0 * PS_S + pc] = make_float2(to_tf32(p00), to_tf32(p01));
            *(float2*)&Ps[rrow1 * PS_S + pc] = make_float2(to_tf32(p10), to_tf32(p11));
        }
        ps0 += __shfl_xor_sync(0xffffffffu, ps0, 1);
        ps0 += __shfl_xor_sync(0xffffffffu, ps0, 2);
        ps1 += __shfl_xor_sync(0xffffffffu, ps1, 1);
        ps1 += __shfl_xor_sync(0xffffffffu, ps1, 2);
        if (tig == 0) {
            red[256 + rrow0 * 2 + nh] = ps0;
            red[256 + rrow1 * 2 + nh] = ps1;
        }

        __syncthreads();    // P + partial sums visible

        l0 = l0 * cor0 + red[256 + rrow0 * 2] + red[256 + rrow0 * 2 + 1];
        l1 = l1 * cor1 + red[256 + rrow1 * 2] + red[256 + rrow1 * 2 + 1];

        #pragma unroll
        for (int j = 0; j < 8; j++) {
            oacc[j][0] *= cor0; oacc[j][1] *= cor0;
            oacc[j][2] *= cor1; oacc[j][3] *= cor1;
        }

        // O += P @ V : warp = 16 rows x 64 d-cols; 8 n8 x 8 k8
        #pragma unroll
        for (int k8 = 0; k8 < 8; k8++) {
            uint32_t a[4];
            ldm_x4(a, PA + k8 * 32);
            #pragma unroll
            for (int nt = 0; nt < 4; nt++) {
                uint32_t b[4];
                ldm_x4(b, VB + (nt * 16 * VT_S + k8 * 8) * 4);
                mma_tf32(oacc[2 * nt],     a, &b[0]);
                mma_tf32(oacc[2 * nt + 1], a, &b[2]);
            }
        }
    }

    // Epilogue: normalize, round to tf32 (feeds out-proj), store
    const float i0 = 1.f / l0, i1 = 1.f / l1;
    float* op0 = out + (size_t)(n * SEQ + row0) * D_MODEL + h * HD + nh * 64;
    float* op1 = out + (size_t)(n * SEQ + row1) * D_MODEL + h * HD + nh * 64;
    #pragma unroll
    for (int j = 0; j < 8; j++) {
        const int c = j * 8 + 2 * tig;
        *(float2*)&op0[c] = make_float2(to_tf32(oacc[j][0] * i0), to_tf32(oacc[j][1] * i0));
        *(float2*)&op1[c] = make_float2(to_tf32(oacc[j][2] * i1), to_tf32(oacc[j][3] * i1));
    }
}

// ---------------------------------------------------------------------------
extern "C" void kernel_launch(void* const* d_in, const int* in_sizes, int n_in,
                              void* d_out, int out_size)
{
    const float* x       = (const float*)d_in[0];
    const float* Wqkv    = (const float*)d_in[1];
    const float* bqkv    = (const float*)d_in[2];
    const float* q_scale = (const float*)d_in[3];
    const float* k_scale = (const float*)d_in[4];
    const float* Wout    = (const float*)d_in[5];
    const float* bout    = (const float*)d_in[6];
    float* out = (float*)d_out;

    float *qkv, *attn, *wqT, *woT;
    cudaGetSymbolAddress((void**)&qkv,  g_qkv);
    cudaGetSymbolAddress((void**)&attn, g_attn);
    cudaGetSymbolAddress((void**)&wqT,  g_wqkvT);
    cudaGetSymbolAddress((void**)&woT,  g_woutT);

    // Prep: transpose+round weights (x rounded in-register inside gemm)
    transpose_tf32<<<dim3(QKVW / 32, KDIM / 32), 256>>>(Wqkv, wqT, KDIM, QKVW);
    transpose_tf32<<<dim3(D_MODEL / 32, KDIM / 32), 256>>>(Wout, woT, KDIM, D_MODEL);

    const int gsmem = GSTG * STAGE_F * 2 * (int)sizeof(float);
    cudaFuncSetAttribute(gemm_mma, cudaFuncAttributeMaxDynamicSharedMemorySize, gsmem);

    // 1) QKV projection (tensor-core tf32)
    gemm_mma<<<dim3(QKVW / 128, TOKENS / 128), 256, gsmem>>>(x, wqT, bqkv, qkv, QKVW, KDIM);

    // 2) RMSNorm q/k heads (rounds outputs to tf32)
    rmsnorm_qk<<<(TOKENS * 20) / 8, 256>>>(qkv, q_scale, k_scale);

    // 3) Tensor-core causal flash attention (512 threads, 16 warps)
    cudaFuncSetAttribute(flash_attn_tc, cudaFuncAttributeMaxDynamicSharedMemorySize, FA_SMEM);
    flash_attn_tc<<<dim3(SEQ / 128, NH, NB), FA_NT, FA_SMEM>>>(qkv, attn);

    // 4) Output projection (tensor-core tf32)
    gemm_mma<<<dim3(D_MODEL / 128, TOKENS / 128), 256, gsmem>>>(attn, woT, bout, out, D_MODEL, KDIM);
}